// round 6
// baseline (speedup 1.0000x reference)
#include <cuda_runtime.h>
#include <cstdint>

// ==================== problem constants ====================
static constexpr int IN_DIM  = 64;
static constexpr int HID     = 128;
static constexpr int OUT_DIM = 64;

static constexpr int THREADS      = 128;   // 4 warps
static constexpr int ROWS_PER_CTA = 128;   // 32 rows per warp

// ==================== smem layout (bytes) ====================
// Wzf : B-fragment-packed Wz  [s:16][lane:32][128B]          = 64KB
// BUF2: Uxf [s:8][lane:32][128B] (32KB), later Wdf [s:16][lane:32][64B] (32KB)
// INJ : per-thread inj segments [thr:128][512B]              = 64KB
// ZS  : per-warp z A-frag buffers [w:4][(mi*16+s)*32+slot][16B] = 64KB
static constexpr int OFF_WZF  = 0;
static constexpr int OFF_BUF2 = 65536;
static constexpr int OFF_INJ  = OFF_BUF2 + 32768;
static constexpr int OFF_ZS   = OFF_INJ + 65536;
static constexpr int SMEM_TOTAL = OFF_ZS + 65536;   // 229376 B

// ==================== small helpers ====================
__device__ __forceinline__ uint32_t f2tf(float f) {
    uint32_t u;
    asm("cvt.rn.tf32.f32 %0, %1;" : "=r"(u) : "f"(f));
    return u;
}

__device__ __forceinline__ void mma_tf32(float* d, const uint32_t* a, const uint32_t* b) {
    asm volatile(
        "mma.sync.aligned.m16n8k8.row.col.f32.tf32.tf32.f32 "
        "{%0,%1,%2,%3},{%4,%5,%6,%7},{%8,%9},{%0,%1,%2,%3};"
        : "+f"(d[0]), "+f"(d[1]), "+f"(d[2]), "+f"(d[3])
        : "r"(a[0]), "r"(a[1]), "r"(a[2]), "r"(a[3]), "r"(b[0]), "r"(b[1]));
}

// slot swizzle for the z A-frag buffer (involution; keeps loads/stores conflict-free)
__device__ __forceinline__ int swz(int l) { return l ^ (((l >> 3) & 1) << 2); }

// ==================== kernel ====================
__global__ void __launch_bounds__(THREADS, 1)
deq_mma_kernel(const float* __restrict__ x,
               const float* __restrict__ Wz,
               const float* __restrict__ Ux,
               const float* __restrict__ b,
               const float* __restrict__ Wd,
               const float* __restrict__ bd,
               const int*   __restrict__ nitp,
               float* __restrict__ out,
               int rows) {
    extern __shared__ char sm[];
    const int tid  = threadIdx.x;
    const int w    = tid >> 5;
    const int lane = tid & 31;
    const int g    = lane >> 2;    // group id (row within 8)
    const int c    = lane & 3;     // thread-in-group (col base)
    const int n_iters = *nitp;

    const long rowbase = (long)blockIdx.x * ROWS_PER_CTA + w * 32;

    // ---------------- pack Wz B-fragments ----------------
    // value(s, ni, lane l): b0 = Wz[8ni+g'][8s+c'], b1 = Wz[8ni+g'][8s+c'+4]
    // addr: (s*32+l)*128 + ((ni>>1)^(l&7))*16 + (ni&1)*8
#pragma unroll 4
    for (int t = 0; t < 64; t++) {
        int idx = t * 128 + tid;            // 0..8191
        int l  = idx & 31;
        int ni = (idx >> 5) & 15;
        int s  = idx >> 9;
        int gg = l >> 2, cc = l & 3;
        const float* src = Wz + (8 * ni + gg) * HID + 8 * s + cc;
        uint32_t v0 = f2tf(src[0]);
        uint32_t v1 = f2tf(src[4]);
        uint32_t addr = OFF_WZF + ((uint32_t)(s * 32 + l) << 7) +
                        ((uint32_t)((ni >> 1) ^ (l & 7)) << 4) + ((uint32_t)(ni & 1) << 3);
        *reinterpret_cast<uint2*>(sm + addr) = make_uint2(v0, v1);
    }
    // ---------------- pack Ux B-fragments (K=64 -> s<8) ----------------
#pragma unroll 4
    for (int t = 0; t < 32; t++) {
        int idx = t * 128 + tid;            // 0..4095
        int l  = idx & 31;
        int ni = (idx >> 5) & 15;
        int s  = idx >> 9;
        int gg = l >> 2, cc = l & 3;
        const float* src = Ux + (8 * ni + gg) * IN_DIM + 8 * s + cc;
        uint32_t v0 = f2tf(src[0]);
        uint32_t v1 = f2tf(src[4]);
        uint32_t addr = OFF_BUF2 + ((uint32_t)(s * 32 + l) << 7) +
                        ((uint32_t)((ni >> 1) ^ (l & 7)) << 4) + ((uint32_t)(ni & 1) << 3);
        *reinterpret_cast<uint2*>(sm + addr) = make_uint2(v0, v1);
    }
    __syncthreads();

    float acc[2][16][4];
#pragma unroll
    for (int mi = 0; mi < 2; mi++)
#pragma unroll
        for (int ni = 0; ni < 16; ni++)
#pragma unroll
            for (int r = 0; r < 4; r++) acc[mi][ni][r] = 0.0f;

    // ---------------- inj = x @ Ux^T  (K = 64) ----------------
#pragma unroll
    for (int s = 0; s < 8; s++) {
        uint32_t A[2][4];
#pragma unroll
        for (int mi = 0; mi < 2; mi++) {
            long r0 = rowbase + 16 * mi + g;
            long r1 = r0 + 8;
            const float* x0 = x + r0 * IN_DIM + 8 * s + c;
            const float* x1 = x + r1 * IN_DIM + 8 * s + c;
            float f0 = (r0 < rows) ? x0[0] : 0.0f;
            float f1 = (r1 < rows) ? x1[0] : 0.0f;
            float f2 = (r0 < rows) ? x0[4] : 0.0f;
            float f3 = (r1 < rows) ? x1[4] : 0.0f;
            A[mi][0] = f2tf(f0); A[mi][1] = f2tf(f1);
            A[mi][2] = f2tf(f2); A[mi][3] = f2tf(f3);
        }
        uint32_t B[16][2];
        const char* bs = sm + OFF_BUF2 + ((uint32_t)(s * 32 + lane) << 7);
#pragma unroll
        for (int j = 0; j < 8; j++) {
            uint4 v = *reinterpret_cast<const uint4*>(bs + ((uint32_t)(j ^ (lane & 7)) << 4));
            B[2 * j][0] = v.x; B[2 * j][1] = v.y;
            B[2 * j + 1][0] = v.z; B[2 * j + 1][1] = v.w;
        }
#pragma unroll
        for (int ni = 0; ni < 16; ni++)
#pragma unroll
            for (int mi = 0; mi < 2; mi++)
                mma_tf32(acc[mi][ni], A[mi], B[ni]);
    }

    // ---------------- inj epilogue: inj = acc + b ; z1 = relu(inj) ----------------
    char* injseg = sm + OFF_INJ + ((uint32_t)tid << 9);
    char* zwarp  = sm + OFF_ZS + ((uint32_t)w << 14);
#pragma unroll
    for (int mi = 0; mi < 2; mi++) {
#pragma unroll
        for (int ni = 0; ni < 16; ni++) {
            float b0v = b[8 * ni + 2 * c];
            float b1v = b[8 * ni + 2 * c + 1];
            float4 v;
            v.x = acc[mi][ni][0] + b0v;
            v.y = acc[mi][ni][1] + b1v;
            v.z = acc[mi][ni][2] + b0v;
            v.w = acc[mi][ni][3] + b1v;
            int q = mi * 16 + ni;
            *reinterpret_cast<float4*>(injseg + ((uint32_t)(q ^ (tid & 7)) << 4)) = v;
            // scatter z = relu(v) into A-frag order
            uint32_t z0 = f2tf(fmaxf(v.x, 0.0f));
            uint32_t z1 = f2tf(fmaxf(v.y, 0.0f));
            uint32_t z2 = f2tf(fmaxf(v.z, 0.0f));
            uint32_t z3 = f2tf(fmaxf(v.w, 0.0f));
            int lt0 = 4 * g + ((c < 2) ? 2 * c : 2 * c - 4);
            int lt1 = 4 * g + ((c < 2) ? 2 * c + 1 : 2 * c - 3);
            int off = (c < 2) ? 0 : 8;
            int cb = q * 32;
            *reinterpret_cast<uint2*>(zwarp + ((uint32_t)(cb + swz(lt0)) << 4) + off) = make_uint2(z0, z2);
            *reinterpret_cast<uint2*>(zwarp + ((uint32_t)(cb + swz(lt1)) << 4) + off) = make_uint2(z1, z3);
        }
    }
    __syncthreads();

    // ---------------- pack Wd B-fragments into BUF2 (K=128, N=64) ----------------
#pragma unroll 4
    for (int t = 0; t < 32; t++) {
        int idx = t * 128 + tid;            // 0..4095 = s*256 + ni*32 + lane
        int l  = idx & 31;
        int ni = (idx >> 5) & 7;
        int s  = idx >> 8;
        int gg = l >> 2, cc = l & 3;
        const float* src = Wd + (8 * ni + gg) * HID + 8 * s + cc;
        uint32_t v0 = f2tf(src[0]);
        uint32_t v1 = f2tf(src[4]);
        int chunk = (ni >> 1) ^ ((l >> 1) & 3);
        uint32_t addr = OFF_BUF2 + ((uint32_t)(s * 32 + l) << 6) +
                        ((uint32_t)chunk << 4) + ((uint32_t)(ni & 1) << 3);
        *reinterpret_cast<uint2*>(sm + addr) = make_uint2(v0, v1);
    }
    __syncthreads();

    // ---------------- fixed-point loop (warp-private, no CTA syncs) ----------------
    for (int it = 1; it < n_iters; it++) {
#pragma unroll
        for (int mi = 0; mi < 2; mi++)
#pragma unroll
            for (int ni = 0; ni < 16; ni++)
#pragma unroll
                for (int r = 0; r < 4; r++) acc[mi][ni][r] = 0.0f;

#pragma unroll
        for (int s = 0; s < 16; s++) {
            uint32_t A[2][4];
#pragma unroll
            for (int mi = 0; mi < 2; mi++) {
                uint4 a = *reinterpret_cast<const uint4*>(
                    zwarp + ((uint32_t)(((mi * 16 + s) * 32) + swz(lane)) << 4));
                A[mi][0] = a.x; A[mi][1] = a.y; A[mi][2] = a.z; A[mi][3] = a.w;
            }
            uint32_t B[16][2];
            const char* bs = sm + OFF_WZF + ((uint32_t)(s * 32 + lane) << 7);
#pragma unroll
            for (int j = 0; j < 8; j++) {
                uint4 v = *reinterpret_cast<const uint4*>(bs + ((uint32_t)(j ^ (lane & 7)) << 4));
                B[2 * j][0] = v.x; B[2 * j][1] = v.y;
                B[2 * j + 1][0] = v.z; B[2 * j + 1][1] = v.w;
            }
#pragma unroll
            for (int ni = 0; ni < 16; ni++)
#pragma unroll
                for (int mi = 0; mi < 2; mi++)
                    mma_tf32(acc[mi][ni], A[mi], B[ni]);
        }

        __syncwarp();   // all A reads done before overwriting z frags
#pragma unroll
        for (int mi = 0; mi < 2; mi++) {
#pragma unroll
            for (int ni = 0; ni < 16; ni++) {
                int q = mi * 16 + ni;
                float4 inj = *reinterpret_cast<const float4*>(
                    injseg + ((uint32_t)(q ^ (tid & 7)) << 4));
                uint32_t z0 = f2tf(fmaxf(acc[mi][ni][0] + inj.x, 0.0f));
                uint32_t z1 = f2tf(fmaxf(acc[mi][ni][1] + inj.y, 0.0f));
                uint32_t z2 = f2tf(fmaxf(acc[mi][ni][2] + inj.z, 0.0f));
                uint32_t z3 = f2tf(fmaxf(acc[mi][ni][3] + inj.w, 0.0f));
                int lt0 = 4 * g + ((c < 2) ? 2 * c : 2 * c - 4);
                int lt1 = 4 * g + ((c < 2) ? 2 * c + 1 : 2 * c - 3);
                int off = (c < 2) ? 0 : 8;
                int cb = q * 32;
                *reinterpret_cast<uint2*>(zwarp + ((uint32_t)(cb + swz(lt0)) << 4) + off) = make_uint2(z0, z2);
                *reinterpret_cast<uint2*>(zwarp + ((uint32_t)(cb + swz(lt1)) << 4) + off) = make_uint2(z1, z3);
            }
        }
        __syncwarp();   // stores visible before next iteration's loads
    }

    // ---------------- decoder: out = z @ Wd^T + bd ----------------
    float acc2[2][8][4];
#pragma unroll
    for (int mi = 0; mi < 2; mi++)
#pragma unroll
        for (int ni = 0; ni < 8; ni++)
#pragma unroll
            for (int r = 0; r < 4; r++) acc2[mi][ni][r] = 0.0f;

#pragma unroll
    for (int s = 0; s < 16; s++) {
        uint32_t A[2][4];
#pragma unroll
        for (int mi = 0; mi < 2; mi++) {
            uint4 a = *reinterpret_cast<const uint4*>(
                zwarp + ((uint32_t)(((mi * 16 + s) * 32) + swz(lane)) << 4));
            A[mi][0] = a.x; A[mi][1] = a.y; A[mi][2] = a.z; A[mi][3] = a.w;
        }
        uint32_t B[8][2];
        const char* bs = sm + OFF_BUF2 + ((uint32_t)(s * 32 + lane) << 6);
#pragma unroll
        for (int j = 0; j < 4; j++) {
            uint4 v = *reinterpret_cast<const uint4*>(
                bs + ((uint32_t)(j ^ ((lane >> 1) & 3)) << 4));
            B[2 * j][0] = v.x; B[2 * j][1] = v.y;
            B[2 * j + 1][0] = v.z; B[2 * j + 1][1] = v.w;
        }
#pragma unroll
        for (int ni = 0; ni < 8; ni++)
#pragma unroll
            for (int mi = 0; mi < 2; mi++)
                mma_tf32(acc2[mi][ni], A[mi], B[ni]);
    }

#pragma unroll
    for (int mi = 0; mi < 2; mi++) {
        long r0 = rowbase + 16 * mi + g;
        long r1 = r0 + 8;
#pragma unroll
        for (int ni = 0; ni < 8; ni++) {
            float bd0 = bd[8 * ni + 2 * c];
            float bd1 = bd[8 * ni + 2 * c + 1];
            if (r0 < rows) {
                float2 v0 = make_float2(acc2[mi][ni][0] + bd0, acc2[mi][ni][1] + bd1);
                *reinterpret_cast<float2*>(out + r0 * OUT_DIM + 8 * ni + 2 * c) = v0;
            }
            if (r1 < rows) {
                float2 v1 = make_float2(acc2[mi][ni][2] + bd0, acc2[mi][ni][3] + bd1);
                *reinterpret_cast<float2*>(out + r1 * OUT_DIM + 8 * ni + 2 * c) = v1;
            }
        }
    }
}

// ==================== launch ====================
extern "C" void kernel_launch(void* const* d_in, const int* in_sizes, int n_in,
                              void* d_out, int out_size) {
    const float* x   = (const float*)d_in[0];
    const float* Wz  = (const float*)d_in[1];
    const float* Ux  = (const float*)d_in[2];
    const float* b   = (const float*)d_in[3];
    const float* Wd  = (const float*)d_in[4];
    const float* bd  = (const float*)d_in[5];
    const int*   nit = (const int*)d_in[6];
    float* out = (float*)d_out;

    int rows = in_sizes[0] / IN_DIM;
    int grid = (rows + ROWS_PER_CTA - 1) / ROWS_PER_CTA;

    cudaFuncSetAttribute(deq_mma_kernel,
                         cudaFuncAttributeMaxDynamicSharedMemorySize, SMEM_TOTAL);

    deq_mma_kernel<<<grid, THREADS, SMEM_TOTAL>>>(x, Wz, Ux, b, Wd, bd, nit, out, rows);
}

// round 7
// speedup vs baseline: 1.2439x; 1.2439x over previous
#include <cuda_runtime.h>
#include <cstdint>

// ==================== problem constants ====================
static constexpr int IN_DIM  = 64;
static constexpr int HID     = 128;
static constexpr int OUT_DIM = 64;

static constexpr int THREADS      = 128;   // 4 warps
static constexpr int ROWS_PER_CTA = 32;    // all 4 warps share the same 32 rows
// SMEM: z A-frag exchange buffer: 32 tiles (mi*16 + s_col) x 32 slots x 16B
static constexpr int SMEM_TOTAL = 32 * 32 * 16;   // 16 KB

// ==================== small helpers ====================
__device__ __forceinline__ uint32_t f2tf(float f) {
    uint32_t u;
    asm("cvt.rn.tf32.f32 %0, %1;" : "=r"(u) : "f"(f));
    return u;
}

__device__ __forceinline__ void mma_tf32(float* d, const uint32_t* a, const uint32_t* b) {
    asm volatile(
        "mma.sync.aligned.m16n8k8.row.col.f32.tf32.tf32.f32 "
        "{%0,%1,%2,%3},{%4,%5,%6,%7},{%8,%9},{%0,%1,%2,%3};"
        : "+f"(d[0]), "+f"(d[1]), "+f"(d[2]), "+f"(d[3])
        : "r"(a[0]), "r"(a[1]), "r"(a[2]), "r"(a[3]), "r"(b[0]), "r"(b[1]));
}

// slot swizzle for the z A-frag buffer (involution; conflict-free loads & stores)
__device__ __forceinline__ int swz(int l) { return l ^ (((l >> 3) & 1) << 2); }

// ==================== kernel ====================
__global__ void __launch_bounds__(THREADS, 2)
deq_mma_kernel(const float* __restrict__ x,
               const float* __restrict__ Wz,
               const float* __restrict__ Ux,
               const float* __restrict__ b,
               const float* __restrict__ Wd,
               const float* __restrict__ bd,
               const int*   __restrict__ nitp,
               float* __restrict__ out,
               int rows) {
    extern __shared__ char sm[];      // 16KB z A-frag buffer (CTA-shared)
    const int tid  = threadIdx.x;
    const int w    = tid >> 5;        // warp owns col slice [32w, 32w+32)
    const int lane = tid & 31;
    const int g    = lane >> 2;       // row-in-8
    const int c    = lane & 3;        // col base-in-4
    const int n_iters = *nitp;

    const long rowbase = (long)blockIdx.x * ROWS_PER_CTA;

    // B-fragment register file: Wz needs [s:16][ni:4] pairs = 128 regs.
    // Reused for Ux ([s:8][ni:4]) before Wz, and Wd ([s:16][ni:2]) after loop.
    uint32_t B[64][2];

    // ---------------- load Ux B-frags (warp's 4 ni tiles, K=64 -> s<8) ----------------
#pragma unroll
    for (int s = 0; s < 8; s++)
#pragma unroll
        for (int ni = 0; ni < 4; ni++) {
            const float* src = Ux + (8 * (4 * w + ni) + g) * IN_DIM + 8 * s + c;
            B[s * 4 + ni][0] = f2tf(__ldg(src));
            B[s * 4 + ni][1] = f2tf(__ldg(src + 4));
        }

    // ---------------- inj = x @ Ux^T + b  (K = 64) ----------------
    float acc[2][4][4];
#pragma unroll
    for (int mi = 0; mi < 2; mi++)
#pragma unroll
        for (int ni = 0; ni < 4; ni++)
#pragma unroll
            for (int r = 0; r < 4; r++) acc[mi][ni][r] = 0.0f;

#pragma unroll
    for (int s = 0; s < 8; s++) {
        uint32_t A[2][4];
#pragma unroll
        for (int mi = 0; mi < 2; mi++) {
            long r0 = rowbase + 16 * mi + g;
            long r1 = r0 + 8;
            const float* x0 = x + r0 * IN_DIM + 8 * s + c;
            const float* x1 = x + r1 * IN_DIM + 8 * s + c;
            float f0 = (r0 < rows) ? x0[0] : 0.0f;
            float f1 = (r1 < rows) ? x1[0] : 0.0f;
            float f2 = (r0 < rows) ? x0[4] : 0.0f;
            float f3 = (r1 < rows) ? x1[4] : 0.0f;
            A[mi][0] = f2tf(f0); A[mi][1] = f2tf(f1);
            A[mi][2] = f2tf(f2); A[mi][3] = f2tf(f3);
        }
#pragma unroll
        for (int ni = 0; ni < 4; ni++)
#pragma unroll
            for (int mi = 0; mi < 2; mi++)
                mma_tf32(acc[mi][ni], A[mi], B[s * 4 + ni]);
    }

    // inj stays in registers; z1 = relu(inj) scattered to the A-frag buffer
    float inj[2][4][4];
#pragma unroll
    for (int ni = 0; ni < 4; ni++) {
        float b0v = __ldg(b + (4 * w + ni) * 8 + 2 * c);
        float b1v = __ldg(b + (4 * w + ni) * 8 + 2 * c + 1);
#pragma unroll
        for (int mi = 0; mi < 2; mi++) {
            inj[mi][ni][0] = acc[mi][ni][0] + b0v;
            inj[mi][ni][1] = acc[mi][ni][1] + b1v;
            inj[mi][ni][2] = acc[mi][ni][2] + b0v;
            inj[mi][ni][3] = acc[mi][ni][3] + b1v;

            uint32_t z0 = f2tf(fmaxf(inj[mi][ni][0], 0.0f));
            uint32_t z1 = f2tf(fmaxf(inj[mi][ni][1], 0.0f));
            uint32_t z2 = f2tf(fmaxf(inj[mi][ni][2], 0.0f));
            uint32_t z3 = f2tf(fmaxf(inj[mi][ni][3], 0.0f));
            int q   = mi * 16 + (4 * w + ni);           // global tile index
            int lt0 = 4 * g + ((c < 2) ? 2 * c : 2 * c - 4);
            int lt1 = 4 * g + ((c < 2) ? 2 * c + 1 : 2 * c - 3);
            int off = (c < 2) ? 0 : 8;
            int cb  = q * 32;
            *reinterpret_cast<uint2*>(sm + ((uint32_t)(cb + swz(lt0)) << 4) + off) = make_uint2(z0, z2);
            *reinterpret_cast<uint2*>(sm + ((uint32_t)(cb + swz(lt1)) << 4) + off) = make_uint2(z1, z3);
        }
    }

    // ---------------- load Wz B-frags into registers (once) ----------------
#pragma unroll
    for (int s = 0; s < 16; s++)
#pragma unroll
        for (int ni = 0; ni < 4; ni++) {
            const float* src = Wz + (8 * (4 * w + ni) + g) * HID + 8 * s + c;
            B[s * 4 + ni][0] = f2tf(__ldg(src));
            B[s * 4 + ni][1] = f2tf(__ldg(src + 4));
        }
    __syncthreads();   // z1 scatter visible to all warps

    // ---------------- fixed-point loop ----------------
    for (int it = 1; it < n_iters; it++) {
#pragma unroll
        for (int mi = 0; mi < 2; mi++)
#pragma unroll
            for (int ni = 0; ni < 4; ni++)
#pragma unroll
                for (int r = 0; r < 4; r++) acc[mi][ni][r] = 0.0f;

#pragma unroll
        for (int s = 0; s < 16; s++) {
            uint32_t A[2][4];
#pragma unroll
            for (int mi = 0; mi < 2; mi++) {
                uint4 a = *reinterpret_cast<const uint4*>(
                    sm + ((uint32_t)(((mi * 16 + s) * 32) + swz(lane)) << 4));
                A[mi][0] = a.x; A[mi][1] = a.y; A[mi][2] = a.z; A[mi][3] = a.w;
            }
#pragma unroll
            for (int ni = 0; ni < 4; ni++)
#pragma unroll
                for (int mi = 0; mi < 2; mi++)
                    mma_tf32(acc[mi][ni], A[mi], B[s * 4 + ni]);
        }
        __syncthreads();   // all A reads done before overwriting z frags

#pragma unroll
        for (int mi = 0; mi < 2; mi++) {
#pragma unroll
            for (int ni = 0; ni < 4; ni++) {
                uint32_t z0 = f2tf(fmaxf(acc[mi][ni][0] + inj[mi][ni][0], 0.0f));
                uint32_t z1 = f2tf(fmaxf(acc[mi][ni][1] + inj[mi][ni][1], 0.0f));
                uint32_t z2 = f2tf(fmaxf(acc[mi][ni][2] + inj[mi][ni][2], 0.0f));
                uint32_t z3 = f2tf(fmaxf(acc[mi][ni][3] + inj[mi][ni][3], 0.0f));
                int q   = mi * 16 + (4 * w + ni);
                int lt0 = 4 * g + ((c < 2) ? 2 * c : 2 * c - 4);
                int lt1 = 4 * g + ((c < 2) ? 2 * c + 1 : 2 * c - 3);
                int off = (c < 2) ? 0 : 8;
                int cb  = q * 32;
                *reinterpret_cast<uint2*>(sm + ((uint32_t)(cb + swz(lt0)) << 4) + off) = make_uint2(z0, z2);
                *reinterpret_cast<uint2*>(sm + ((uint32_t)(cb + swz(lt1)) << 4) + off) = make_uint2(z1, z3);
            }
        }
        __syncthreads();   // stores visible before next iteration's loads
    }

    // ---------------- decoder: out = z @ Wd^T + bd ----------------
    // warp w computes cols [16w, 16w+16): ni 0..1, rows 8*(2w+ni)+g of Wd
#pragma unroll
    for (int s = 0; s < 16; s++)
#pragma unroll
        for (int ni = 0; ni < 2; ni++) {
            const float* src = Wd + (8 * (2 * w + ni) + g) * HID + 8 * s + c;
            B[s * 2 + ni][0] = f2tf(__ldg(src));
            B[s * 2 + ni][1] = f2tf(__ldg(src + 4));
        }

    float acc2[2][2][4];
#pragma unroll
    for (int mi = 0; mi < 2; mi++)
#pragma unroll
        for (int ni = 0; ni < 2; ni++)
#pragma unroll
            for (int r = 0; r < 4; r++) acc2[mi][ni][r] = 0.0f;

#pragma unroll
    for (int s = 0; s < 16; s++) {
        uint32_t A[2][4];
#pragma unroll
        for (int mi = 0; mi < 2; mi++) {
            uint4 a = *reinterpret_cast<const uint4*>(
                sm + ((uint32_t)(((mi * 16 + s) * 32) + swz(lane)) << 4));
            A[mi][0] = a.x; A[mi][1] = a.y; A[mi][2] = a.z; A[mi][3] = a.w;
        }
#pragma unroll
        for (int ni = 0; ni < 2; ni++)
#pragma unroll
            for (int mi = 0; mi < 2; mi++)
                mma_tf32(acc2[mi][ni], A[mi], B[s * 2 + ni]);
    }

#pragma unroll
    for (int mi = 0; mi < 2; mi++) {
        long r0 = rowbase + 16 * mi + g;
        long r1 = r0 + 8;
#pragma unroll
        for (int ni = 0; ni < 2; ni++) {
            int colb = 16 * w + 8 * ni + 2 * c;
            float bd0 = __ldg(bd + colb);
            float bd1 = __ldg(bd + colb + 1);
            if (r0 < rows) {
                float2 v0 = make_float2(acc2[mi][ni][0] + bd0, acc2[mi][ni][1] + bd1);
                *reinterpret_cast<float2*>(out + r0 * OUT_DIM + colb) = v0;
            }
            if (r1 < rows) {
                float2 v1 = make_float2(acc2[mi][ni][2] + bd0, acc2[mi][ni][3] + bd1);
                *reinterpret_cast<float2*>(out + r1 * OUT_DIM + colb) = v1;
            }
        }
    }
}

// ==================== launch ====================
extern "C" void kernel_launch(void* const* d_in, const int* in_sizes, int n_in,
                              void* d_out, int out_size) {
    const float* x   = (const float*)d_in[0];
    const float* Wz  = (const float*)d_in[1];
    const float* Ux  = (const float*)d_in[2];
    const float* b   = (const float*)d_in[3];
    const float* Wd  = (const float*)d_in[4];
    const float* bd  = (const float*)d_in[5];
    const int*   nit = (const int*)d_in[6];
    float* out = (float*)d_out;

    int rows = in_sizes[0] / IN_DIM;
    int grid = (rows + ROWS_PER_CTA - 1) / ROWS_PER_CTA;

    deq_mma_kernel<<<grid, THREADS, SMEM_TOTAL>>>(x, Wz, Ux, b, Wd, bd, nit, out, rows);
}

// round 8
// speedup vs baseline: 1.2543x; 1.0084x over previous
#include <cuda_runtime.h>
#include <cstdint>

// ==================== problem constants ====================
static constexpr int IN_DIM  = 64;
static constexpr int HID     = 128;
static constexpr int OUT_DIM = 64;

static constexpr int THREADS      = 128;   // 4 warps
static constexpr int ROWS_PER_CTA = 32;    // all 4 warps share the same 32 rows
// SMEM: double-buffered z A-frag exchange: 2 x [32 tiles x 32 slots x 16B]
static constexpr int BUF_BYTES  = 32 * 32 * 16;       // 16 KB
static constexpr int SMEM_TOTAL = 2 * BUF_BYTES;      // 32 KB

// ==================== small helpers ====================
__device__ __forceinline__ uint32_t f2tf(float f) {
    uint32_t u;
    asm("cvt.rn.tf32.f32 %0, %1;" : "=r"(u) : "f"(f));
    return u;
}

__device__ __forceinline__ void mma_tf32(float* d, const uint32_t* a, const uint32_t* b) {
    asm volatile(
        "mma.sync.aligned.m16n8k8.row.col.f32.tf32.tf32.f32 "
        "{%0,%1,%2,%3},{%4,%5,%6,%7},{%8,%9},{%0,%1,%2,%3};"
        : "+f"(d[0]), "+f"(d[1]), "+f"(d[2]), "+f"(d[3])
        : "r"(a[0]), "r"(a[1]), "r"(a[2]), "r"(a[3]), "r"(b[0]), "r"(b[1]));
}

// slot swizzle for the z A-frag buffer (involution; conflict-free loads & stores)
__device__ __forceinline__ int swz(int l) { return l ^ (((l >> 3) & 1) << 2); }

// ==================== kernel ====================
__global__ void __launch_bounds__(THREADS, 2)
deq_mma_kernel(const float* __restrict__ x,
               const float* __restrict__ Wz,
               const float* __restrict__ Ux,
               const float* __restrict__ b,
               const float* __restrict__ Wd,
               const float* __restrict__ bd,
               const int*   __restrict__ nitp,
               float* __restrict__ out,
               int rows) {
    extern __shared__ char sm[];      // 2 x 16KB z A-frag buffers
    const int tid  = threadIdx.x;
    const int w    = tid >> 5;        // warp owns col slice [32w, 32w+32)
    const int lane = tid & 31;
    const int g    = lane >> 2;       // row-in-8
    const int c    = lane & 3;        // col base-in-4
    const int n_iters = *nitp;

    const long rowbase = (long)blockIdx.x * ROWS_PER_CTA;

    // precomputed scatter constants (C-frag -> A-frag slot mapping)
    const int lt0  = 4 * g + ((c < 2) ? 2 * c : 2 * c - 4);
    const int lt1  = lt0 + 1;
    const int offc = (c < 2) ? 0 : 8;
    const uint32_t st0 = ((uint32_t)swz(lt0) << 4) + offc;
    const uint32_t st1 = ((uint32_t)swz(lt1) << 4) + offc;

    // B-fragment register file: Wz needs [s:16][ni:4] pairs = 128 regs.
    // Reused for Ux ([s:8][ni:4]) before Wz, and Wd ([s:16][ni:2]) after loop.
    uint32_t B[64][2];

    // ---------------- load Ux B-frags (warp's 4 ni tiles, K=64 -> s<8) ----------------
#pragma unroll
    for (int s = 0; s < 8; s++)
#pragma unroll
        for (int ni = 0; ni < 4; ni++) {
            const float* src = Ux + (8 * (4 * w + ni) + g) * IN_DIM + 8 * s + c;
            B[s * 4 + ni][0] = f2tf(__ldg(src));
            B[s * 4 + ni][1] = f2tf(__ldg(src + 4));
        }

    // ---------------- inj = x @ Ux^T + b  (K = 64) ----------------
    float acc[2][4][4];
#pragma unroll
    for (int mi = 0; mi < 2; mi++)
#pragma unroll
        for (int ni = 0; ni < 4; ni++)
#pragma unroll
            for (int r = 0; r < 4; r++) acc[mi][ni][r] = 0.0f;

#pragma unroll
    for (int s = 0; s < 8; s++) {
        uint32_t A[2][4];
#pragma unroll
        for (int mi = 0; mi < 2; mi++) {
            long r0 = rowbase + 16 * mi + g;
            long r1 = r0 + 8;
            const float* x0 = x + r0 * IN_DIM + 8 * s + c;
            const float* x1 = x + r1 * IN_DIM + 8 * s + c;
            float f0 = (r0 < rows) ? x0[0] : 0.0f;
            float f1 = (r1 < rows) ? x1[0] : 0.0f;
            float f2 = (r0 < rows) ? x0[4] : 0.0f;
            float f3 = (r1 < rows) ? x1[4] : 0.0f;
            A[mi][0] = f2tf(f0); A[mi][1] = f2tf(f1);
            A[mi][2] = f2tf(f2); A[mi][3] = f2tf(f3);
        }
#pragma unroll
        for (int ni = 0; ni < 4; ni++)
#pragma unroll
            for (int mi = 0; mi < 2; mi++)
                mma_tf32(acc[mi][ni], A[mi], B[s * 4 + ni]);
    }

    // inj stays in registers; z1 = relu(inj) scattered into buffer 0
    float inj[2][4][4];
#pragma unroll
    for (int ni = 0; ni < 4; ni++) {
        float b0v = __ldg(b + (4 * w + ni) * 8 + 2 * c);
        float b1v = __ldg(b + (4 * w + ni) * 8 + 2 * c + 1);
#pragma unroll
        for (int mi = 0; mi < 2; mi++) {
            inj[mi][ni][0] = acc[mi][ni][0] + b0v;
            inj[mi][ni][1] = acc[mi][ni][1] + b1v;
            inj[mi][ni][2] = acc[mi][ni][2] + b0v;
            inj[mi][ni][3] = acc[mi][ni][3] + b1v;

            uint32_t z0 = f2tf(fmaxf(inj[mi][ni][0], 0.0f));
            uint32_t z1 = f2tf(fmaxf(inj[mi][ni][1], 0.0f));
            uint32_t z2 = f2tf(fmaxf(inj[mi][ni][2], 0.0f));
            uint32_t z3 = f2tf(fmaxf(inj[mi][ni][3], 0.0f));
            uint32_t cb = (uint32_t)((mi * 16 + (4 * w + ni)) * 32) << 4;
            *reinterpret_cast<uint2*>(sm + cb + st0) = make_uint2(z0, z2);
            *reinterpret_cast<uint2*>(sm + cb + st1) = make_uint2(z1, z3);
        }
    }

    // ---------------- load Wz B-frags into registers (once) ----------------
#pragma unroll
    for (int s = 0; s < 16; s++)
#pragma unroll
        for (int ni = 0; ni < 4; ni++) {
            const float* src = Wz + (8 * (4 * w + ni) + g) * HID + 8 * s + c;
            B[s * 4 + ni][0] = f2tf(__ldg(src));
            B[s * 4 + ni][1] = f2tf(__ldg(src + 4));
        }
    __syncthreads();   // z1 scatter visible to all warps

    // ---------------- fixed-point loop: double-buffered, ONE sync/iter ----------------
    char* rd = sm;               // read buffer
    char* wr = sm + BUF_BYTES;   // write buffer
    for (int it = 1; it < n_iters; it++) {
        // acc starts at inj (folds the injection add into the accumulator)
#pragma unroll
        for (int mi = 0; mi < 2; mi++)
#pragma unroll
            for (int ni = 0; ni < 4; ni++)
#pragma unroll
                for (int r = 0; r < 4; r++) acc[mi][ni][r] = inj[mi][ni][r];

#pragma unroll
        for (int s = 0; s < 16; s++) {
            uint32_t A[2][4];
#pragma unroll
            for (int mi = 0; mi < 2; mi++) {
                uint4 a = *reinterpret_cast<const uint4*>(
                    rd + ((uint32_t)(((mi * 16 + s) * 32) + swz(lane)) << 4));
                A[mi][0] = a.x; A[mi][1] = a.y; A[mi][2] = a.z; A[mi][3] = a.w;
            }
#pragma unroll
            for (int ni = 0; ni < 4; ni++)
#pragma unroll
                for (int mi = 0; mi < 2; mi++)
                    mma_tf32(acc[mi][ni], A[mi], B[s * 4 + ni]);
        }

        // write z = relu(acc) into the other buffer (no hazard with readers of rd)
#pragma unroll
        for (int mi = 0; mi < 2; mi++) {
#pragma unroll
            for (int ni = 0; ni < 4; ni++) {
                uint32_t z0 = f2tf(fmaxf(acc[mi][ni][0], 0.0f));
                uint32_t z1 = f2tf(fmaxf(acc[mi][ni][1], 0.0f));
                uint32_t z2 = f2tf(fmaxf(acc[mi][ni][2], 0.0f));
                uint32_t z3 = f2tf(fmaxf(acc[mi][ni][3], 0.0f));
                uint32_t cb = (uint32_t)((mi * 16 + (4 * w + ni)) * 32) << 4;
                *reinterpret_cast<uint2*>(wr + cb + st0) = make_uint2(z0, z2);
                *reinterpret_cast<uint2*>(wr + cb + st1) = make_uint2(z1, z3);
            }
        }
        __syncthreads();   // writes to wr visible; everyone flips
        char* t = rd; rd = wr; wr = t;
    }

    // ---------------- decoder: out = z @ Wd^T + bd ----------------
    // warp w computes cols [16w, 16w+16): ni 0..1, rows 8*(2w+ni)+g of Wd
#pragma unroll
    for (int s = 0; s < 16; s++)
#pragma unroll
        for (int ni = 0; ni < 2; ni++) {
            const float* src = Wd + (8 * (2 * w + ni) + g) * HID + 8 * s + c;
            B[s * 2 + ni][0] = f2tf(__ldg(src));
            B[s * 2 + ni][1] = f2tf(__ldg(src + 4));
        }

    float acc2[2][2][4];
#pragma unroll
    for (int mi = 0; mi < 2; mi++)
#pragma unroll
        for (int ni = 0; ni < 2; ni++)
#pragma unroll
            for (int r = 0; r < 4; r++) acc2[mi][ni][r] = 0.0f;

#pragma unroll
    for (int s = 0; s < 16; s++) {
        uint32_t A[2][4];
#pragma unroll
        for (int mi = 0; mi < 2; mi++) {
            uint4 a = *reinterpret_cast<const uint4*>(
                rd + ((uint32_t)(((mi * 16 + s) * 32) + swz(lane)) << 4));
            A[mi][0] = a.x; A[mi][1] = a.y; A[mi][2] = a.z; A[mi][3] = a.w;
        }
#pragma unroll
        for (int ni = 0; ni < 2; ni++)
#pragma unroll
            for (int mi = 0; mi < 2; mi++)
                mma_tf32(acc2[mi][ni], A[mi], B[s * 2 + ni]);
    }

#pragma unroll
    for (int mi = 0; mi < 2; mi++) {
        long r0 = rowbase + 16 * mi + g;
        long r1 = r0 + 8;
#pragma unroll
        for (int ni = 0; ni < 2; ni++) {
            int colb = 16 * w + 8 * ni + 2 * c;
            float bd0 = __ldg(bd + colb);
            float bd1 = __ldg(bd + colb + 1);
            if (r0 < rows) {
                float2 v0 = make_float2(acc2[mi][ni][0] + bd0, acc2[mi][ni][1] + bd1);
                *reinterpret_cast<float2*>(out + r0 * OUT_DIM + colb) = v0;
            }
            if (r1 < rows) {
                float2 v1 = make_float2(acc2[mi][ni][2] + bd0, acc2[mi][ni][3] + bd1);
                *reinterpret_cast<float2*>(out + r1 * OUT_DIM + colb) = v1;
            }
        }
    }
}

// ==================== launch ====================
extern "C" void kernel_launch(void* const* d_in, const int* in_sizes, int n_in,
                              void* d_out, int out_size) {
    const float* x   = (const float*)d_in[0];
    const float* Wz  = (const float*)d_in[1];
    const float* Ux  = (const float*)d_in[2];
    const float* b   = (const float*)d_in[3];
    const float* Wd  = (const float*)d_in[4];
    const float* bd  = (const float*)d_in[5];
    const int*   nit = (const int*)d_in[6];
    float* out = (float*)d_out;

    int rows = in_sizes[0] / IN_DIM;
    int grid = (rows + ROWS_PER_CTA - 1) / ROWS_PER_CTA;

    deq_mma_kernel<<<grid, THREADS, SMEM_TOTAL>>>(x, Wz, Ux, b, Wd, bd, nit, out, rows);
}

// round 9
// speedup vs baseline: 1.4038x; 1.1191x over previous
#include <cuda_runtime.h>
#include <cstdint>

// ==================== problem constants ====================
static constexpr int IN_DIM  = 64;
static constexpr int HID     = 128;
static constexpr int OUT_DIM = 64;

static constexpr int THREADS      = 128;   // 4 warps
static constexpr int MI           = 4;     // 4 x 16 = 64 rows per CTA
static constexpr int ROWS_PER_CTA = 16 * MI;
// z A-frag exchange, double buffered: 64 tiles x 32 slots x 16B per buffer
static constexpr int BUF_BYTES  = (MI * 16) * 32 * 16;   // 32 KB
static constexpr int SMEM_TOTAL = 2 * BUF_BYTES;         // 64 KB

// ==================== small helpers ====================
__device__ __forceinline__ uint32_t f2tf(float f) {
    uint32_t u;
    asm("cvt.rn.tf32.f32 %0, %1;" : "=r"(u) : "f"(f));
    return u;
}

__device__ __forceinline__ void mma_tf32(float* d, const uint32_t* a, const uint32_t* b) {
    asm volatile(
        "mma.sync.aligned.m16n8k8.row.col.f32.tf32.tf32.f32 "
        "{%0,%1,%2,%3},{%4,%5,%6,%7},{%8,%9},{%0,%1,%2,%3};"
        : "+f"(d[0]), "+f"(d[1]), "+f"(d[2]), "+f"(d[3])
        : "r"(a[0]), "r"(a[1]), "r"(a[2]), "r"(a[3]), "r"(b[0]), "r"(b[1]));
}

// slot swizzle (involution; conflict-free LDS.128 loads & STS.64 stores)
__device__ __forceinline__ int swz(int l) { return l ^ (((l >> 3) & 1) << 2); }

// ==================== kernel ====================
__global__ void __launch_bounds__(THREADS, 2)
deq_mma_kernel(const float* __restrict__ x,
               const float* __restrict__ Wz,
               const float* __restrict__ Ux,
               const float* __restrict__ b,
               const float* __restrict__ Wd,
               const float* __restrict__ bd,
               const int*   __restrict__ nitp,
               float* __restrict__ out,
               int rows) {
    extern __shared__ char sm[];      // 2 x 32KB z A-frag buffers
    const int tid  = threadIdx.x;
    const int w    = tid >> 5;        // warp owns col slice [32w, 32w+32)
    const int lane = tid & 31;
    const int g    = lane >> 2;       // row-in-8
    const int c    = lane & 3;        // col base-in-4
    const int n_iters = *nitp;

    const long rowbase = (long)blockIdx.x * ROWS_PER_CTA;

    // scatter constants (C-frag -> A-frag slot mapping)
    const int lt0  = 4 * g + ((c < 2) ? 2 * c : 2 * c - 4);
    const int lt1  = lt0 + 1;
    const int offc = (c < 2) ? 0 : 8;
    const uint32_t st0 = ((uint32_t)swz(lt0) << 4) + offc;
    const uint32_t st1 = ((uint32_t)swz(lt1) << 4) + offc;
    const uint32_t lanerd = (uint32_t)swz(lane) << 4;   // A-load lane offset

    // B-fragment register file (reused: Ux -> Wz -> Wd)
    uint32_t B[64][2];

    // ---------------- load Ux B-frags (warp's 4 ni tiles, K=64 -> s<8) ----------------
#pragma unroll
    for (int s = 0; s < 8; s++)
#pragma unroll
        for (int ni = 0; ni < 4; ni++) {
            const float* src = Ux + (8 * (4 * w + ni) + g) * IN_DIM + 8 * s + c;
            B[s * 4 + ni][0] = f2tf(__ldg(src));
            B[s * 4 + ni][1] = f2tf(__ldg(src + 4));
        }

    // ---------------- inj = x @ Ux^T + b (computed straight into inj regs) ----------------
    float inj[MI][4][4];
#pragma unroll
    for (int mi = 0; mi < MI; mi++)
#pragma unroll
        for (int ni = 0; ni < 4; ni++)
#pragma unroll
            for (int r = 0; r < 4; r++) inj[mi][ni][r] = 0.0f;

#pragma unroll
    for (int s = 0; s < 8; s++) {
        uint32_t A[MI][4];
#pragma unroll
        for (int mi = 0; mi < MI; mi++) {
            long r0 = rowbase + 16 * mi + g;
            long r1 = r0 + 8;
            const float* x0 = x + r0 * IN_DIM + 8 * s + c;
            const float* x1 = x + r1 * IN_DIM + 8 * s + c;
            float f0 = (r0 < rows) ? x0[0] : 0.0f;
            float f1 = (r1 < rows) ? x1[0] : 0.0f;
            float f2 = (r0 < rows) ? x0[4] : 0.0f;
            float f3 = (r1 < rows) ? x1[4] : 0.0f;
            A[mi][0] = f2tf(f0); A[mi][1] = f2tf(f1);
            A[mi][2] = f2tf(f2); A[mi][3] = f2tf(f3);
        }
#pragma unroll
        for (int ni = 0; ni < 4; ni++)
#pragma unroll
            for (int mi = 0; mi < MI; mi++)
                mma_tf32(inj[mi][ni], A[mi], B[s * 4 + ni]);
    }

    // add bias; scatter z1 = relu(inj) into buffer 0
#pragma unroll
    for (int ni = 0; ni < 4; ni++) {
        float b0v = __ldg(b + (4 * w + ni) * 8 + 2 * c);
        float b1v = __ldg(b + (4 * w + ni) * 8 + 2 * c + 1);
#pragma unroll
        for (int mi = 0; mi < MI; mi++) {
            inj[mi][ni][0] += b0v;
            inj[mi][ni][1] += b1v;
            inj[mi][ni][2] += b0v;
            inj[mi][ni][3] += b1v;

            uint32_t z0 = f2tf(fmaxf(inj[mi][ni][0], 0.0f));
            uint32_t z1 = f2tf(fmaxf(inj[mi][ni][1], 0.0f));
            uint32_t z2 = f2tf(fmaxf(inj[mi][ni][2], 0.0f));
            uint32_t z3 = f2tf(fmaxf(inj[mi][ni][3], 0.0f));
            uint32_t cb = (uint32_t)((mi * 16 + (4 * w + ni)) * 32) << 4;
            *reinterpret_cast<uint2*>(sm + cb + st0) = make_uint2(z0, z2);
            *reinterpret_cast<uint2*>(sm + cb + st1) = make_uint2(z1, z3);
        }
    }

    // ---------------- load Wz B-frags into registers (once) ----------------
#pragma unroll
    for (int s = 0; s < 16; s++)
#pragma unroll
        for (int ni = 0; ni < 4; ni++) {
            const float* src = Wz + (8 * (4 * w + ni) + g) * HID + 8 * s + c;
            B[s * 4 + ni][0] = f2tf(__ldg(src));
            B[s * 4 + ni][1] = f2tf(__ldg(src + 4));
        }
    __syncthreads();   // z1 scatter visible to all warps

    // ---------------- fixed-point loop: mi-split pipeline, one sync/iter ----------------
    char* rd = sm;
    char* wr = sm + BUF_BYTES;
    for (int it = 1; it < n_iters; it++) {
#pragma unroll
        for (int mi = 0; mi < MI; mi++) {
            // acc starts at inj (injection folded into accumulator init)
            float acc[4][4];
#pragma unroll
            for (int ni = 0; ni < 4; ni++)
#pragma unroll
                for (int r = 0; r < 4; r++) acc[ni][r] = inj[mi][ni][r];

            const char* rdm = rd + (uint32_t)(mi * 16 * 32) * 16u;
#pragma unroll
            for (int s = 0; s < 16; s++) {
                uint4 a = *reinterpret_cast<const uint4*>(rdm + (uint32_t)(s * 512) + lanerd);
                uint32_t A[4] = {a.x, a.y, a.z, a.w};
#pragma unroll
                for (int ni = 0; ni < 4; ni++)
                    mma_tf32(acc[ni], A, B[s * 4 + ni]);
            }

            // epilogue for this mi (stores overlap next mi's MMAs)
#pragma unroll
            for (int ni = 0; ni < 4; ni++) {
                uint32_t z0 = f2tf(fmaxf(acc[ni][0], 0.0f));
                uint32_t z1 = f2tf(fmaxf(acc[ni][1], 0.0f));
                uint32_t z2 = f2tf(fmaxf(acc[ni][2], 0.0f));
                uint32_t z3 = f2tf(fmaxf(acc[ni][3], 0.0f));
                uint32_t cb = (uint32_t)((mi * 16 + (4 * w + ni)) * 32) << 4;
                *reinterpret_cast<uint2*>(wr + cb + st0) = make_uint2(z0, z2);
                *reinterpret_cast<uint2*>(wr + cb + st1) = make_uint2(z1, z3);
            }
        }
        __syncthreads();
        char* t = rd; rd = wr; wr = t;
    }

    // ---------------- decoder: out = z @ Wd^T + bd ----------------
    // warp w computes cols [16w, 16w+16): ni 0..1
#pragma unroll
    for (int s = 0; s < 16; s++)
#pragma unroll
        for (int ni = 0; ni < 2; ni++) {
            const float* src = Wd + (8 * (2 * w + ni) + g) * HID + 8 * s + c;
            B[s * 2 + ni][0] = f2tf(__ldg(src));
            B[s * 2 + ni][1] = f2tf(__ldg(src + 4));
        }

#pragma unroll
    for (int mi = 0; mi < MI; mi++) {
        float acc2[2][4];
#pragma unroll
        for (int ni = 0; ni < 2; ni++)
#pragma unroll
            for (int r = 0; r < 4; r++) acc2[ni][r] = 0.0f;

        const char* rdm = rd + (uint32_t)(mi * 16 * 32) * 16u;
#pragma unroll
        for (int s = 0; s < 16; s++) {
            uint4 a = *reinterpret_cast<const uint4*>(rdm + (uint32_t)(s * 512) + lanerd);
            uint32_t A[4] = {a.x, a.y, a.z, a.w};
#pragma unroll
            for (int ni = 0; ni < 2; ni++)
                mma_tf32(acc2[ni], A, B[s * 2 + ni]);
        }

        long r0 = rowbase + 16 * mi + g;
        long r1 = r0 + 8;
#pragma unroll
        for (int ni = 0; ni < 2; ni++) {
            int colb = 16 * w + 8 * ni + 2 * c;
            float bd0 = __ldg(bd + colb);
            float bd1 = __ldg(bd + colb + 1);
            if (r0 < rows) {
                float2 v0 = make_float2(acc2[ni][0] + bd0, acc2[ni][1] + bd1);
                *reinterpret_cast<float2*>(out + r0 * OUT_DIM + colb) = v0;
            }
            if (r1 < rows) {
                float2 v1 = make_float2(acc2[ni][2] + bd0, acc2[ni][3] + bd1);
                *reinterpret_cast<float2*>(out + r1 * OUT_DIM + colb) = v1;
            }
        }
    }
}

// ==================== launch ====================
extern "C" void kernel_launch(void* const* d_in, const int* in_sizes, int n_in,
                              void* d_out, int out_size) {
    const float* x   = (const float*)d_in[0];
    const float* Wz  = (const float*)d_in[1];
    const float* Ux  = (const float*)d_in[2];
    const float* b   = (const float*)d_in[3];
    const float* Wd  = (const float*)d_in[4];
    const float* bd  = (const float*)d_in[5];
    const int*   nit = (const int*)d_in[6];
    float* out = (float*)d_out;

    int rows = in_sizes[0] / IN_DIM;
    int grid = (rows + ROWS_PER_CTA - 1) / ROWS_PER_CTA;

    cudaFuncSetAttribute(deq_mma_kernel,
                         cudaFuncAttributeMaxDynamicSharedMemorySize, SMEM_TOTAL);

    deq_mma_kernel<<<grid, THREADS, SMEM_TOTAL>>>(x, Wz, Ux, b, Wd, bd, nit, out, rows);
}

// round 11
// speedup vs baseline: 2.7858x; 1.9845x over previous
#include <cuda_runtime.h>
#include <cstdint>

// ==================== problem constants ====================
static constexpr int IN_DIM  = 64;
static constexpr int HID     = 128;
static constexpr int OUT_DIM = 64;

static constexpr int THREADS      = 128;   // 4 warps
static constexpr int MI           = 4;     // 4 x 16 = 64 rows per CTA
static constexpr int ROWS_PER_CTA = 16 * MI;
static constexpr int KS           = HID / 16;   // 8 k-steps of 16
// z exchange (fp16 A-frags), double buffered: (MI*KS) tiles x 32 slots x 16B
static constexpr int BUF_BYTES  = (MI * KS) * 32 * 16;   // 16 KB
static constexpr int SMEM_TOTAL = 2 * BUF_BYTES;         // 32 KB

// ==================== small helpers ====================
__device__ __forceinline__ uint32_t pack_h2(float lo, float hi) {
    uint32_t d;
    asm("cvt.rn.f16x2.f32 %0, %1, %2;" : "=r"(d) : "f"(hi), "f"(lo));
    return d;
}
__device__ __forceinline__ uint32_t pack_h2_relu(float lo, float hi) {
    uint32_t d;
    asm("cvt.rn.relu.f16x2.f32 %0, %1, %2;" : "=r"(d) : "f"(hi), "f"(lo));
    return d;
}

// D(f32) += A(f16 m16n8k16) * B(f16)
__device__ __forceinline__ void mma_f16(float* d, const uint32_t* a, const uint32_t* b) {
    asm volatile(
        "mma.sync.aligned.m16n8k16.row.col.f32.f16.f16.f32 "
        "{%0,%1,%2,%3},{%4,%5,%6,%7},{%8,%9},{%0,%1,%2,%3};"
        : "+f"(d[0]), "+f"(d[1]), "+f"(d[2]), "+f"(d[3])
        : "r"(a[0]), "r"(a[1]), "r"(a[2]), "r"(a[3]), "r"(b[0]), "r"(b[1]));
}

// slot swizzle (involution; conflict-free LDS.128 loads & STS.64 stores)
__device__ __forceinline__ int swz(int l) { return l ^ (((l >> 3) & 1) << 2); }

// ==================== kernel ====================
__global__ void __launch_bounds__(THREADS, 2)
deq_mma_kernel(const float* __restrict__ x,
               const float* __restrict__ Wz,
               const float* __restrict__ Ux,
               const float* __restrict__ b,
               const float* __restrict__ Wd,
               const float* __restrict__ bd,
               const int*   __restrict__ nitp,
               float* __restrict__ out,
               int rows) {
    extern __shared__ char sm[];      // 2 x 16KB fp16 z A-frag buffers
    const int tid  = threadIdx.x;
    const int w    = tid >> 5;        // warp owns col slice [32w, 32w+32)
    const int lane = tid & 31;
    const int g    = lane >> 2;       // row-in-8 (groupID)
    const int c    = lane & 3;        // threadID-in-group
    const int n_iters = *nitp;

    const long rowbase = (long)blockIdx.x * ROWS_PER_CTA;
    const uint32_t lanerd = (uint32_t)swz(lane) << 4;   // own 16B slot offset

    // B-fragment register file (fp16x2 pairs). Wz: [s:8][ni:4] = 64 regs.
    // Reused: Ux [s:4][ni:4], Wd [s:8][ni:2].
    uint32_t B[32][2];

    // ---------------- load Ux B-frags (K=64 -> 4 k-steps) ----------------
#pragma unroll
    for (int s = 0; s < 4; s++)
#pragma unroll
        for (int ni = 0; ni < 4; ni++) {
            const float* src = Ux + (32 * w + 8 * ni + g) * IN_DIM + 16 * s + 2 * c;
            B[s * 4 + ni][0] = pack_h2(__ldg(src),     __ldg(src + 1));
            B[s * 4 + ni][1] = pack_h2(__ldg(src + 8), __ldg(src + 9));
        }

    // ---------------- inj = x @ Ux^T (straight into inj regs) ----------------
    float inj[MI][4][4];
#pragma unroll
    for (int mi = 0; mi < MI; mi++)
#pragma unroll
        for (int ni = 0; ni < 4; ni++)
#pragma unroll
            for (int r = 0; r < 4; r++) inj[mi][ni][r] = 0.0f;

#pragma unroll
    for (int s = 0; s < 4; s++) {
        uint32_t A[MI][4];
#pragma unroll
        for (int mi = 0; mi < MI; mi++) {
            long r0 = rowbase + 16 * mi + g;
            long r1 = r0 + 8;
            const float* x0 = x + r0 * IN_DIM + 16 * s + 2 * c;
            const float* x1 = x + r1 * IN_DIM + 16 * s + 2 * c;
            float2 p0 = (r0 < rows) ? *reinterpret_cast<const float2*>(x0)     : make_float2(0.f, 0.f);
            float2 p1 = (r1 < rows) ? *reinterpret_cast<const float2*>(x1)     : make_float2(0.f, 0.f);
            float2 p2 = (r0 < rows) ? *reinterpret_cast<const float2*>(x0 + 8) : make_float2(0.f, 0.f);
            float2 p3 = (r1 < rows) ? *reinterpret_cast<const float2*>(x1 + 8) : make_float2(0.f, 0.f);
            A[mi][0] = pack_h2(p0.x, p0.y);
            A[mi][1] = pack_h2(p1.x, p1.y);
            A[mi][2] = pack_h2(p2.x, p2.y);
            A[mi][3] = pack_h2(p3.x, p3.y);
        }
#pragma unroll
        for (int ni = 0; ni < 4; ni++)
#pragma unroll
            for (int mi = 0; mi < MI; mi++)
                mma_f16(inj[mi][ni], A[mi], B[s * 4 + ni]);
    }

    // add bias; scatter z1 = relu(inj) into buffer 0 (fp16, one STS.64 per tile)
    // tile index for producer cols [32w + 8ni, +8) is 2w + (ni>>1)  (16-col tiles)
#pragma unroll
    for (int ni = 0; ni < 4; ni++) {
        float b0v = __ldg(b + 32 * w + 8 * ni + 2 * c);
        float b1v = __ldg(b + 32 * w + 8 * ni + 2 * c + 1);
#pragma unroll
        for (int mi = 0; mi < MI; mi++) {
            inj[mi][ni][0] += b0v;
            inj[mi][ni][1] += b1v;
            inj[mi][ni][2] += b0v;
            inj[mi][ni][3] += b1v;
            uint2 v;
            v.x = pack_h2_relu(inj[mi][ni][0], inj[mi][ni][1]);   // a0,a1 (or a2,a3) rows g,g+8
            v.y = pack_h2_relu(inj[mi][ni][2], inj[mi][ni][3]);
            uint32_t tile = (uint32_t)(mi * KS + 2 * w + (ni >> 1));
            uint32_t addr = tile * 512u + lanerd + ((uint32_t)(ni & 1) << 3);
            *reinterpret_cast<uint2*>(sm + addr) = v;
        }
    }

    // ---------------- load Wz B-frags (once; K=128 -> 8 k-steps) ----------------
#pragma unroll
    for (int s = 0; s < KS; s++)
#pragma unroll
        for (int ni = 0; ni < 4; ni++) {
            const float* src = Wz + (32 * w + 8 * ni + g) * HID + 16 * s + 2 * c;
            B[s * 4 + ni][0] = pack_h2(__ldg(src),     __ldg(src + 1));
            B[s * 4 + ni][1] = pack_h2(__ldg(src + 8), __ldg(src + 9));
        }
    __syncthreads();   // z1 scatter visible to all warps

    // ---------------- fixed-point loop: mi-split pipeline, one sync/iter ----------------
    char* rd = sm;
    char* wr = sm + BUF_BYTES;
    for (int it = 1; it < n_iters; it++) {
#pragma unroll
        for (int mi = 0; mi < MI; mi++) {
            float acc[4][4];
#pragma unroll
            for (int ni = 0; ni < 4; ni++)
#pragma unroll
                for (int r = 0; r < 4; r++) acc[ni][r] = inj[mi][ni][r];

            const char* rdm = rd + (uint32_t)(mi * KS * 512);
#pragma unroll
            for (int s = 0; s < KS; s++) {
                uint4 a = *reinterpret_cast<const uint4*>(rdm + (uint32_t)(s * 512) + lanerd);
                uint32_t A[4] = {a.x, a.y, a.z, a.w};
#pragma unroll
                for (int ni = 0; ni < 4; ni++)
                    mma_f16(acc[ni], A, B[s * 4 + ni]);
            }

            // epilogue for this mi (stores overlap next mi's MMAs)
            char* wrm = wr + (uint32_t)(mi * KS * 512);
#pragma unroll
            for (int ni = 0; ni < 4; ni++) {
                uint2 v;
                v.x = pack_h2_relu(acc[ni][0], acc[ni][1]);
                v.y = pack_h2_relu(acc[ni][2], acc[ni][3]);
                uint32_t tile = (uint32_t)(2 * w + (ni >> 1));
                uint32_t addr = tile * 512u + lanerd + ((uint32_t)(ni & 1) << 3);
                *reinterpret_cast<uint2*>(wrm + addr) = v;
            }
        }
        __syncthreads();
        char* t = rd; rd = wr; wr = t;
    }

    // ---------------- decoder: out = z @ Wd^T + bd ----------------
    // warp w computes cols [16w, 16w+16): ni 0..1
#pragma unroll
    for (int s = 0; s < KS; s++)
#pragma unroll
        for (int ni = 0; ni < 2; ni++) {
            const float* src = Wd + (16 * w + 8 * ni + g) * HID + 16 * s + 2 * c;
            B[s * 2 + ni][0] = pack_h2(__ldg(src),     __ldg(src + 1));
            B[s * 2 + ni][1] = pack_h2(__ldg(src + 8), __ldg(src + 9));
        }

#pragma unroll
    for (int mi = 0; mi < MI; mi++) {
        float acc2[2][4];
#pragma unroll
        for (int ni = 0; ni < 2; ni++)
#pragma unroll
            for (int r = 0; r < 4; r++) acc2[ni][r] = 0.0f;

        const char* rdm = rd + (uint32_t)(mi * KS * 512);
#pragma unroll
        for (int s = 0; s < KS; s++) {
            uint4 a = *reinterpret_cast<const uint4*>(rdm + (uint32_t)(s * 512) + lanerd);
            uint32_t A[4] = {a.x, a.y, a.z, a.w};
#pragma unroll
            for (int ni = 0; ni < 2; ni++)
                mma_f16(acc2[ni], A, B[s * 2 + ni]);
        }

        long r0 = rowbase + 16 * mi + g;
        long r1 = r0 + 8;
#pragma unroll
        for (int ni = 0; ni < 2; ni++) {
            int colb = 16 * w + 8 * ni + 2 * c;
            float bd0 = __ldg(bd + colb);
            float bd1 = __ldg(bd + colb + 1);
            if (r0 < rows) {
                float2 v0 = make_float2(acc2[ni][0] + bd0, acc2[ni][1] + bd1);
                *reinterpret_cast<float2*>(out + r0 * OUT_DIM + colb) = v0;
            }
            if (r1 < rows) {
                float2 v1 = make_float2(acc2[ni][2] + bd0, acc2[ni][3] + bd1);
                *reinterpret_cast<float2*>(out + r1 * OUT_DIM + colb) = v1;
            }
        }
    }
}

// ==================== launch ====================
extern "C" void kernel_launch(void* const* d_in, const int* in_sizes, int n_in,
                              void* d_out, int out_size) {
    const float* x   = (const float*)d_in[0];
    const float* Wz  = (const float*)d_in[1];
    const float* Ux  = (const float*)d_in[2];
    const float* b   = (const float*)d_in[3];
    const float* Wd  = (const float*)d_in[4];
    const float* bd  = (const float*)d_in[5];
    const int*   nit = (const int*)d_in[6];
    float* out = (float*)d_out;

    int rows = in_sizes[0] / IN_DIM;
    int grid = (rows + ROWS_PER_CTA - 1) / ROWS_PER_CTA;

    deq_mma_kernel<<<grid, THREADS, SMEM_TOTAL>>>(x, Wz, Ux, b, Wd, bd, nit, out, rows);
}

// round 12
// speedup vs baseline: 2.8611x; 1.0270x over previous
#include <cuda_runtime.h>
#include <cstdint>

// ==================== problem constants ====================
static constexpr int IN_DIM  = 64;
static constexpr int HID     = 128;
static constexpr int OUT_DIM = 64;

static constexpr int THREADS      = 128;   // 4 warps
static constexpr int MI           = 8;     // 8 x 16 = 128 rows per CTA
static constexpr int ROWS_PER_CTA = 16 * MI;
static constexpr int KS           = HID / 16;   // 8 k-steps of 16
// z exchange (fp16 A-frags), double buffered: (MI*KS) tiles x 32 slots x 16B
static constexpr int BUF_BYTES  = (MI * KS) * 32 * 16;   // 32 KB
static constexpr int SMEM_TOTAL = 2 * BUF_BYTES;         // 64 KB

// ==================== small helpers ====================
__device__ __forceinline__ uint32_t pack_h2(float lo, float hi) {
    uint32_t d;
    asm("cvt.rn.f16x2.f32 %0, %1, %2;" : "=r"(d) : "f"(hi), "f"(lo));
    return d;
}
__device__ __forceinline__ uint32_t pack_h2_relu(float lo, float hi) {
    uint32_t d;
    asm("cvt.rn.relu.f16x2.f32 %0, %1, %2;" : "=r"(d) : "f"(hi), "f"(lo));
    return d;
}

// D(f32) += A(f16 m16n8k16) * B(f16)
__device__ __forceinline__ void mma_f16(float* d, const uint32_t* a, const uint32_t* b) {
    asm volatile(
        "mma.sync.aligned.m16n8k16.row.col.f32.f16.f16.f32 "
        "{%0,%1,%2,%3},{%4,%5,%6,%7},{%8,%9},{%0,%1,%2,%3};"
        : "+f"(d[0]), "+f"(d[1]), "+f"(d[2]), "+f"(d[3])
        : "r"(a[0]), "r"(a[1]), "r"(a[2]), "r"(a[3]), "r"(b[0]), "r"(b[1]));
}

// slot swizzle (involution; conflict-free LDS.128 loads & STS.64 stores)
__device__ __forceinline__ int swz(int l) { return l ^ (((l >> 3) & 1) << 2); }

// ==================== kernel ====================
__global__ void __launch_bounds__(THREADS, 2)
deq_mma_kernel(const float* __restrict__ x,
               const float* __restrict__ Wz,
               const float* __restrict__ Ux,
               const float* __restrict__ b,
               const float* __restrict__ Wd,
               const float* __restrict__ bd,
               const int*   __restrict__ nitp,
               float* __restrict__ out,
               int rows) {
    extern __shared__ char sm[];      // 2 x 32KB fp16 z A-frag buffers
    const int tid  = threadIdx.x;
    const int w    = tid >> 5;        // warp owns col slice [32w, 32w+32)
    const int lane = tid & 31;
    const int g    = lane >> 2;       // row-in-8 (groupID)
    const int c    = lane & 3;        // threadID-in-group
    const int n_iters = *nitp;

    const long rowbase = (long)blockIdx.x * ROWS_PER_CTA;
    const uint32_t lanerd = (uint32_t)swz(lane) << 4;   // own 16B slot offset

    // B-fragment register file (fp16x2 pairs). Wz: [s:8][ni:4] = 64 regs.
    // Reused: Ux [s:4][ni:4], Wd [s:8][ni:2].
    uint32_t B[32][2];

    // ---------------- load Ux B-frags (K=64 -> 4 k-steps) ----------------
#pragma unroll
    for (int s = 0; s < 4; s++)
#pragma unroll
        for (int ni = 0; ni < 4; ni++) {
            const float* src = Ux + (32 * w + 8 * ni + g) * IN_DIM + 16 * s + 2 * c;
            B[s * 4 + ni][0] = pack_h2(__ldg(src),     __ldg(src + 1));
            B[s * 4 + ni][1] = pack_h2(__ldg(src + 8), __ldg(src + 9));
        }

    // ---------------- inj = x @ Ux^T (straight into inj regs) ----------------
    float inj[MI][4][4];
#pragma unroll
    for (int mi = 0; mi < MI; mi++)
#pragma unroll
        for (int ni = 0; ni < 4; ni++)
#pragma unroll
            for (int r = 0; r < 4; r++) inj[mi][ni][r] = 0.0f;

#pragma unroll
    for (int s = 0; s < 4; s++) {
#pragma unroll
        for (int mi = 0; mi < MI; mi++) {
            uint32_t A[4];
            long r0 = rowbase + 16 * mi + g;
            long r1 = r0 + 8;
            const float* x0 = x + r0 * IN_DIM + 16 * s + 2 * c;
            const float* x1 = x + r1 * IN_DIM + 16 * s + 2 * c;
            float2 p0 = (r0 < rows) ? *reinterpret_cast<const float2*>(x0)     : make_float2(0.f, 0.f);
            float2 p1 = (r1 < rows) ? *reinterpret_cast<const float2*>(x1)     : make_float2(0.f, 0.f);
            float2 p2 = (r0 < rows) ? *reinterpret_cast<const float2*>(x0 + 8) : make_float2(0.f, 0.f);
            float2 p3 = (r1 < rows) ? *reinterpret_cast<const float2*>(x1 + 8) : make_float2(0.f, 0.f);
            A[0] = pack_h2(p0.x, p0.y);
            A[1] = pack_h2(p1.x, p1.y);
            A[2] = pack_h2(p2.x, p2.y);
            A[3] = pack_h2(p3.x, p3.y);
#pragma unroll
            for (int ni = 0; ni < 4; ni++)
                mma_f16(inj[mi][ni], A, B[s * 4 + ni]);
        }
    }

    // add bias; scatter z1 = relu(inj) into buffer 0 (fp16, one STS.64 per tile)
    // tile index for producer cols [32w + 8ni, +8) is 2w + (ni>>1)  (16-col tiles)
#pragma unroll
    for (int ni = 0; ni < 4; ni++) {
        float b0v = __ldg(b + 32 * w + 8 * ni + 2 * c);
        float b1v = __ldg(b + 32 * w + 8 * ni + 2 * c + 1);
#pragma unroll
        for (int mi = 0; mi < MI; mi++) {
            inj[mi][ni][0] += b0v;
            inj[mi][ni][1] += b1v;
            inj[mi][ni][2] += b0v;
            inj[mi][ni][3] += b1v;
            uint2 v;
            v.x = pack_h2_relu(inj[mi][ni][0], inj[mi][ni][1]);   // rows g, g+8 cols 2c(+1)
            v.y = pack_h2_relu(inj[mi][ni][2], inj[mi][ni][3]);   // cols +8
            uint32_t tile = (uint32_t)(mi * KS + 2 * w + (ni >> 1));
            uint32_t addr = tile * 512u + lanerd + ((uint32_t)(ni & 1) << 3);
            *reinterpret_cast<uint2*>(sm + addr) = v;
        }
    }

    // ---------------- load Wz B-frags (once; K=128 -> 8 k-steps) ----------------
#pragma unroll
    for (int s = 0; s < KS; s++)
#pragma unroll
        for (int ni = 0; ni < 4; ni++) {
            const float* src = Wz + (32 * w + 8 * ni + g) * HID + 16 * s + 2 * c;
            B[s * 4 + ni][0] = pack_h2(__ldg(src),     __ldg(src + 1));
            B[s * 4 + ni][1] = pack_h2(__ldg(src + 8), __ldg(src + 9));
        }
    __syncthreads();   // z1 scatter visible to all warps

    // ---------------- fixed-point loop: mi-split pipeline, one sync/iter ----------------
    char* rd = sm;
    char* wr = sm + BUF_BYTES;
    for (int it = 1; it < n_iters; it++) {
#pragma unroll
        for (int mi = 0; mi < MI; mi++) {
            float acc[4][4];
#pragma unroll
            for (int ni = 0; ni < 4; ni++)
#pragma unroll
                for (int r = 0; r < 4; r++) acc[ni][r] = inj[mi][ni][r];

            const char* rdm = rd + (uint32_t)(mi * KS * 512);
#pragma unroll
            for (int s = 0; s < KS; s++) {
                uint4 a = *reinterpret_cast<const uint4*>(rdm + (uint32_t)(s * 512) + lanerd);
                uint32_t A[4] = {a.x, a.y, a.z, a.w};
#pragma unroll
                for (int ni = 0; ni < 4; ni++)
                    mma_f16(acc[ni], A, B[s * 4 + ni]);
            }

            // epilogue for this mi (stores overlap next mi's MMAs)
            char* wrm = wr + (uint32_t)(mi * KS * 512);
#pragma unroll
            for (int ni = 0; ni < 4; ni++) {
                uint2 v;
                v.x = pack_h2_relu(acc[ni][0], acc[ni][1]);
                v.y = pack_h2_relu(acc[ni][2], acc[ni][3]);
                uint32_t tile = (uint32_t)(2 * w + (ni >> 1));
                uint32_t addr = tile * 512u + lanerd + ((uint32_t)(ni & 1) << 3);
                *reinterpret_cast<uint2*>(wrm + addr) = v;
            }
        }
        __syncthreads();
        char* t = rd; rd = wr; wr = t;
    }

    // ---------------- decoder: out = z @ Wd^T + bd ----------------
    // warp w computes cols [16w, 16w+16): ni 0..1
#pragma unroll
    for (int s = 0; s < KS; s++)
#pragma unroll
        for (int ni = 0; ni < 2; ni++) {
            const float* src = Wd + (16 * w + 8 * ni + g) * HID + 16 * s + 2 * c;
            B[s * 2 + ni][0] = pack_h2(__ldg(src),     __ldg(src + 1));
            B[s * 2 + ni][1] = pack_h2(__ldg(src + 8), __ldg(src + 9));
        }

#pragma unroll
    for (int mi = 0; mi < MI; mi++) {
        float acc2[2][4];
#pragma unroll
        for (int ni = 0; ni < 2; ni++)
#pragma unroll
            for (int r = 0; r < 4; r++) acc2[ni][r] = 0.0f;

        const char* rdm = rd + (uint32_t)(mi * KS * 512);
#pragma unroll
        for (int s = 0; s < KS; s++) {
            uint4 a = *reinterpret_cast<const uint4*>(rdm + (uint32_t)(s * 512) + lanerd);
            uint32_t A[4] = {a.x, a.y, a.z, a.w};
#pragma unroll
            for (int ni = 0; ni < 2; ni++)
                mma_f16(acc2[ni], A, B[s * 2 + ni]);
        }

        long r0 = rowbase + 16 * mi + g;
        long r1 = r0 + 8;
#pragma unroll
        for (int ni = 0; ni < 2; ni++) {
            int colb = 16 * w + 8 * ni + 2 * c;
            float bd0 = __ldg(bd + colb);
            float bd1 = __ldg(bd + colb + 1);
            if (r0 < rows) {
                float2 v0 = make_float2(acc2[ni][0] + bd0, acc2[ni][1] + bd1);
                *reinterpret_cast<float2*>(out + r0 * OUT_DIM + colb) = v0;
            }
            if (r1 < rows) {
                float2 v1 = make_float2(acc2[ni][2] + bd0, acc2[ni][3] + bd1);
                *reinterpret_cast<float2*>(out + r1 * OUT_DIM + colb) = v1;
            }
        }
    }
}

// ==================== launch ====================
extern "C" void kernel_launch(void* const* d_in, const int* in_sizes, int n_in,
                              void* d_out, int out_size) {
    const float* x   = (const float*)d_in[0];
    const float* Wz  = (const float*)d_in[1];
    const float* Ux  = (const float*)d_in[2];
    const float* b   = (const float*)d_in[3];
    const float* Wd  = (const float*)d_in[4];
    const float* bd  = (const float*)d_in[5];
    const int*   nit = (const int*)d_in[6];
    float* out = (float*)d_out;

    int rows = in_sizes[0] / IN_DIM;
    int grid = (rows + ROWS_PER_CTA - 1) / ROWS_PER_CTA;

    cudaFuncSetAttribute(deq_mma_kernel,
                         cudaFuncAttributeMaxDynamicSharedMemorySize, SMEM_TOTAL);

    deq_mma_kernel<<<grid, THREADS, SMEM_TOTAL>>>(x, Wz, Ux, b, Wd, bd, nit, out, rows);
}